// round 13
// baseline (speedup 1.0000x reference)
#include <cuda_runtime.h>
#include <cuda_bf16.h>
#include <cuda_fp16.h>
#include <cstdint>

#define B_ 32
#define M_ 8192
#define QN 64
#define DN 128
#define S_CHUNKS 8
#define CHUNK 1024
#define MT 64
#define NT 16
#define THREADS 256

#define ROW  256   // A/C/U/H row bytes (128 elems x 2B), XOR-swizzled 16B granules
#define PROW 128   // P row bytes (64 elems x 2B)

// shared memory byte offsets (107520+1024 B -> 2 CTAs/SM)
#define A_HI 0
#define A_LO 16384
#define C_F  32768
#define U_HI 49152
#define U_LO 65536
#define P_HI 81920
#define P_LO 90112
#define H_HI 98304
#define H_LO 102400
#define RED_OFF 106496
#define SMEM_TOTAL (106496 + 1024)

// partial sums: [b*S_CHUNKS+chunk][q*DN+d]  (8.4 MB)
__device__ float g_part[(size_t)B_ * S_CHUNKS * QN * DN];

__device__ __forceinline__ uint32_t smem_u32(const void* p) {
    uint32_t a;
    asm("{ .reg .u64 t; cvta.to.shared.u64 t, %1; cvt.u32.u64 %0, t; }" : "=r"(a) : "l"(p));
    return a;
}
__device__ __forceinline__ uint32_t swz(uint32_t r, uint32_t g) {
    return r * ROW + ((g ^ (r & 7)) << 4);
}
__device__ __forceinline__ uint32_t swzp(uint32_t r, uint32_t g) {
    return r * PROW + ((g ^ (r & 7)) << 4);
}
__device__ __forceinline__ void ldsm4(uint32_t* r, uint32_t a) {
    asm volatile("ldmatrix.sync.aligned.m8n8.x4.shared.b16 {%0,%1,%2,%3}, [%4];"
                 : "=r"(r[0]), "=r"(r[1]), "=r"(r[2]), "=r"(r[3]) : "r"(a));
}
__device__ __forceinline__ void ldsm4t(uint32_t* r, uint32_t a) {
    asm volatile("ldmatrix.sync.aligned.m8n8.x4.trans.shared.b16 {%0,%1,%2,%3}, [%4];"
                 : "=r"(r[0]), "=r"(r[1]), "=r"(r[2]), "=r"(r[3]) : "r"(a));
}
__device__ __forceinline__ void mma_bf16(float* d, const uint32_t* a, const uint32_t* b) {
    asm volatile(
        "mma.sync.aligned.m16n8k16.row.col.f32.bf16.bf16.f32 "
        "{%0,%1,%2,%3}, {%4,%5,%6,%7}, {%8,%9}, {%0,%1,%2,%3};"
        : "+f"(d[0]), "+f"(d[1]), "+f"(d[2]), "+f"(d[3])
        : "r"(a[0]), "r"(a[1]), "r"(a[2]), "r"(a[3]), "r"(b[0]), "r"(b[1]));
}
__device__ __forceinline__ void mma_f16(float* d, const uint32_t* a, const uint32_t* b) {
    asm volatile(
        "mma.sync.aligned.m16n8k16.row.col.f32.f16.f16.f32 "
        "{%0,%1,%2,%3}, {%4,%5,%6,%7}, {%8,%9}, {%0,%1,%2,%3};"
        : "+f"(d[0]), "+f"(d[1]), "+f"(d[2]), "+f"(d[3])
        : "r"(a[0]), "r"(a[1]), "r"(a[2]), "r"(a[3]), "r"(b[0]), "r"(b[1]));
}
// bf16 hi/lo split (packed pairs)
__device__ __forceinline__ void cvt2(float x0, float x1, uint32_t& hi, uint32_t& lo) {
    __nv_bfloat162 h = __float22bfloat162_rn(make_float2(x0, x1));
    hi = *reinterpret_cast<uint32_t*>(&h);
    float h0 = __uint_as_float(hi << 16);
    float h1 = __uint_as_float(hi & 0xFFFF0000u);
    __nv_bfloat162 l = __float22bfloat162_rn(make_float2(x0 - h0, x1 - h1));
    lo = *reinterpret_cast<uint32_t*>(&l);
}
// fp16 single pack
__device__ __forceinline__ uint32_t cvth(float x0, float x1) {
    __half2 h = __float22half2_rn(make_float2(x0, x1));
    return *reinterpret_cast<uint32_t*>(&h);
}
// fp16 hi/lo split (packed pairs)
__device__ __forceinline__ void cvt2h(float x0, float x1, uint32_t& hi, uint32_t& lo) {
    __half2 h = __float22half2_rn(make_float2(x0, x1));
    hi = *reinterpret_cast<uint32_t*>(&h);
    float h0 = __half2float(__low2half(h));
    float h1 = __half2float(__high2half(h));
    __half2 l = __float22half2_rn(make_float2(x0 - h0, x1 - h1));
    lo = *reinterpret_cast<uint32_t*>(&l);
}

// ---------------------------------------------------------------------------
__global__ __launch_bounds__(THREADS, 2) void attn_mma(
    const float* __restrict__ story_a, const float* __restrict__ u,
    const float* __restrict__ story_c, const float* __restrict__ Hm)
{
    extern __shared__ char sm[];
    const uint32_t sb = smem_u32(sm);
    float2* red = reinterpret_cast<float2*>(sm + RED_OFF);   // [row][qh]
    const int tid = threadIdx.x, lane = tid & 31, wid = tid >> 5;
    const int b = blockIdx.y, chunk = blockIdx.x;
    const int m_base_g = chunk * CHUNK;

    // ---- stage u (64q x 128d), bf16 hi/lo, swizzled ----
    {
        const float4* g4 = reinterpret_cast<const float4*>(u + (size_t)b * QN * DN);
        for (int i = tid; i < QN * DN / 4; i += THREADS) {
            int q = i >> 5, j = i & 31;
            float4 v = g4[i];
            uint32_t h0, l0, h1, l1;
            cvt2(v.x, v.y, h0, l0); cvt2(v.z, v.w, h1, l1);
            uint32_t off = swz(q, j >> 1) + (j & 1) * 8;
            *reinterpret_cast<uint2*>(sm + U_HI + off) = make_uint2(h0, h1);
            *reinterpret_cast<uint2*>(sm + U_LO + off) = make_uint2(l0, l1);
        }
    }
    // ---- stage H slice (16d x 128e), rows = d in [chunk*16, chunk*16+16) ----
    {
        const float4* g4 = reinterpret_cast<const float4*>(Hm) + chunk * 16 * 32;
        for (int i = tid; i < 16 * DN / 4; i += THREADS) {
            int r = i >> 5, j = i & 31;
            float4 v = g4[i];
            uint32_t h0, l0, h1, l1;
            cvt2(v.x, v.y, h0, l0); cvt2(v.z, v.w, h1, l1);
            uint32_t off = swz(r, j >> 1) + (j & 1) * 8;
            *reinterpret_cast<uint2*>(sm + H_HI + off) = make_uint2(h0, h1);
            *reinterpret_cast<uint2*>(sm + H_LO + off) = make_uint2(l0, l1);
        }
    }

    // GEMM1: warp = 16m x 32q.
    const int mg = wid & 3, qh = wid >> 2;
    const uint32_t a1_row = (uint32_t)(mg * 16 + (lane & 15));
    const uint32_t a1_gh  = (lane & 16) ? 1u : 0u;
    const uint32_t b1_row = (uint32_t)((lane & 7) + ((lane & 16) ? 8 : 0));
    const uint32_t b1_gh  = (lane & 8) ? 1u : 0u;
    // GEMM2: warp = 16q x 64d.
    const int qg = wid & 3, dh = wid >> 2;
    const uint32_t pa_row = (uint32_t)((lane & 7) + ((lane & 16) ? 8 : 0));
    const uint32_t pa_g   = (uint32_t)(qg * 2 + ((lane & 8) ? 1 : 0));
    const uint32_t cb_row = (uint32_t)((lane & 7) + ((lane & 8) ? 8 : 0));
    const uint32_t cb_gh  = (lane & 16) ? 1u : 0u;

    float cacc[8][4];
#pragma unroll
    for (int i = 0; i < 8; ++i)
#pragma unroll
        for (int j = 0; j < 4; ++j) cacc[i][j] = 0.f;

    for (int t = 0; t < NT; ++t) {
        // ---- prefetch story_a tile into registers BEFORE the barrier ----
        const float4* ga = reinterpret_cast<const float4*>(
            story_a + ((size_t)b * M_ + m_base_g + t * MT) * DN);
        const float4* gc = reinterpret_cast<const float4*>(
            story_c + ((size_t)b * M_ + m_base_g + t * MT) * DN);
        float4 a_pre[8];
#pragma unroll
        for (int k = 0; k < 8; ++k) a_pre[k] = ga[tid + k * THREADS];

        __syncthreads();   // previous tile fully consumed

        // ---- issue story_c loads, then convert+store A (hides C latency) ----
        {
            float4 c_pre[8];
#pragma unroll
            for (int k = 0; k < 8; ++k) c_pre[k] = gc[tid + k * THREADS];
#pragma unroll
            for (int k = 0; k < 8; ++k) {
                int i = tid + k * THREADS;
                int m = i >> 5, j = i & 31;
                uint32_t off = swz(m, j >> 1) + (j & 1) * 8;
                uint32_t h0, l0, h1, l1;
                cvt2(a_pre[k].x, a_pre[k].y, h0, l0);
                cvt2(a_pre[k].z, a_pre[k].w, h1, l1);
                *reinterpret_cast<uint2*>(sm + A_HI + off) = make_uint2(h0, h1);
                *reinterpret_cast<uint2*>(sm + A_LO + off) = make_uint2(l0, l1);
            }
#pragma unroll
            for (int k = 0; k < 8; ++k) {
                int i = tid + k * THREADS;
                int m = i >> 5, j = i & 31;
                uint32_t off = swz(m, j >> 1) + (j & 1) * 8;
                *reinterpret_cast<uint2*>(sm + C_F + off) =
                    make_uint2(cvth(c_pre[k].x, c_pre[k].y), cvth(c_pre[k].z, c_pre[k].w));
            }
        }
        __syncthreads();

        // ---- GEMM1: S[16m][32q], bf16 3-pass, K=128, A-frag double-buffered ----
        float s[4][4];
#pragma unroll
        for (int i = 0; i < 4; ++i)
#pragma unroll
            for (int j = 0; j < 4; ++j) s[i][j] = 0.f;

        uint32_t ahb[2][4], alb[2][4];
        {
            uint32_t a0 = sb + A_HI + swz(a1_row, a1_gh);
            ldsm4(ahb[0], a0);
            ldsm4(alb[0], a0 + (A_LO - A_HI));
        }
#pragma unroll
        for (int ks = 0; ks < 8; ++ks) {
            const int cur = ks & 1, nxt = cur ^ 1;
            if (ks < 7) {
                uint32_t an = sb + A_HI + swz(a1_row, (uint32_t)(ks + 1) * 2 + a1_gh);
                ldsm4(ahb[nxt], an);
                ldsm4(alb[nxt], an + (A_LO - A_HI));
            }
#pragma unroll
            for (int ntp = 0; ntp < 2; ++ntp) {
                uint32_t bh[4], bl[4];
                uint32_t baddr = sb + U_HI
                    + swz((uint32_t)(qh * 32 + ntp * 16) + b1_row, (uint32_t)ks * 2 + b1_gh);
                ldsm4(bh, baddr);
                ldsm4(bl, baddr + (U_LO - U_HI));
#pragma unroll
                for (int j = 0; j < 2; ++j) {
                    mma_bf16(s[ntp * 2 + j], ahb[cur], bh + 2 * j);
                    mma_bf16(s[ntp * 2 + j], ahb[cur], bl + 2 * j);
                    mma_bf16(s[ntp * 2 + j], alb[cur], bh + 2 * j);
                }
            }
        }

        // ---- softmax over q: local stats + one-barrier cross-half merge ----
        {
            const uint32_t r1 = (uint32_t)(mg * 16 + (lane >> 2)), r2 = r1 + 8;
            float mx1 = -1e30f, mx2 = -1e30f;
#pragma unroll
            for (int nt = 0; nt < 4; ++nt) {
                mx1 = fmaxf(mx1, fmaxf(s[nt][0], s[nt][1]));
                mx2 = fmaxf(mx2, fmaxf(s[nt][2], s[nt][3]));
            }
            mx1 = fmaxf(mx1, __shfl_xor_sync(0xffffffffu, mx1, 1));
            mx1 = fmaxf(mx1, __shfl_xor_sync(0xffffffffu, mx1, 2));
            mx2 = fmaxf(mx2, __shfl_xor_sync(0xffffffffu, mx2, 1));
            mx2 = fmaxf(mx2, __shfl_xor_sync(0xffffffffu, mx2, 2));
            float sum1 = 0.f, sum2 = 0.f;
#pragma unroll
            for (int nt = 0; nt < 4; ++nt) {
                s[nt][0] = __expf(s[nt][0] - mx1); sum1 += s[nt][0];
                s[nt][1] = __expf(s[nt][1] - mx1); sum1 += s[nt][1];
                s[nt][2] = __expf(s[nt][2] - mx2); sum2 += s[nt][2];
                s[nt][3] = __expf(s[nt][3] - mx2); sum2 += s[nt][3];
            }
            sum1 += __shfl_xor_sync(0xffffffffu, sum1, 1);
            sum1 += __shfl_xor_sync(0xffffffffu, sum1, 2);
            sum2 += __shfl_xor_sync(0xffffffffu, sum2, 1);
            sum2 += __shfl_xor_sync(0xffffffffu, sum2, 2);
            if ((lane & 3) == 0) {
                red[r1 * 2 + qh] = make_float2(mx1, sum1);
                red[r2 * 2 + qh] = make_float2(mx2, sum2);
            }
            __syncthreads();
            float2 o1 = red[r1 * 2 + (1 - qh)];
            float2 o2 = red[r2 * 2 + (1 - qh)];
            float g1 = fmaxf(mx1, o1.x), g2 = fmaxf(mx2, o2.x);
            float e1 = __expf(mx1 - g1), e2 = __expf(mx2 - g2);
            float f1 = e1 / (sum1 * e1 + o1.y * __expf(o1.x - g1));
            float f2 = e2 / (sum2 * e2 + o2.y * __expf(o2.x - g2));

            const uint32_t qb = (uint32_t)(lane & 3) * 4;
#pragma unroll
            for (int nt = 0; nt < 4; ++nt) {
                uint32_t h, l;
                uint32_t g = (uint32_t)(qh * 4 + nt);
                uint32_t o1b = swzp(r1, g) + qb;
                uint32_t o2b = swzp(r2, g) + qb;
                cvt2h(s[nt][0] * f1, s[nt][1] * f1, h, l);
                *reinterpret_cast<uint32_t*>(sm + P_HI + o1b) = h;
                *reinterpret_cast<uint32_t*>(sm + P_LO + o1b) = l;
                cvt2h(s[nt][2] * f2, s[nt][3] * f2, h, l);
                *reinterpret_cast<uint32_t*>(sm + P_HI + o2b) = h;
                *reinterpret_cast<uint32_t*>(sm + P_LO + o2b) = l;
            }
        }
        __syncthreads();

        // ---- GEMM2: C[16q][64d] += P^T * SC, fp16 2-pass, K=64 ----
        uint32_t phb[2][4], plb[2][4];
        {
            uint32_t p0 = sb + P_HI + swzp(pa_row, pa_g);
            ldsm4t(phb[0], p0);
            ldsm4t(plb[0], p0 + (P_LO - P_HI));
        }
#pragma unroll
        for (int ks = 0; ks < 4; ++ks) {
            const int cur = ks & 1, nxt = cur ^ 1;
            if (ks < 3) {
                uint32_t pn = sb + P_HI + swzp((uint32_t)(ks + 1) * 16 + pa_row, pa_g);
                ldsm4t(phb[nxt], pn);
                ldsm4t(plb[nxt], pn + (P_LO - P_HI));
            }
#pragma unroll
            for (int ntp = 0; ntp < 4; ++ntp) {
                uint32_t bf[4];
                uint32_t baddr = sb + C_F
                    + swz((uint32_t)ks * 16 + cb_row, (uint32_t)(dh * 8 + ntp * 2) + cb_gh);
                ldsm4t(bf, baddr);
#pragma unroll
                for (int j = 0; j < 2; ++j) {
                    mma_f16(cacc[ntp * 2 + j], phb[cur], bf + 2 * j);
                    mma_f16(cacc[ntp * 2 + j], plb[cur], bf + 2 * j);
                }
            }
        }
    }

    // ---- uH k-slice: cacc[q][e] += u[q, 16c:16c+16] @ H[16c:16c+16, e] ----
    // A = u (bf16 hi/lo, ldsm4 at granule 2*chunk), B = H slice (trans-ldsm).
    {
        uint32_t uhf[4], ulf[4];
        uint32_t ua = sb + U_HI + swz((uint32_t)(qg * 16) + (uint32_t)(lane & 15),
                                      (uint32_t)(chunk * 2) + a1_gh);
        ldsm4(uhf, ua);
        ldsm4(ulf, ua + (U_LO - U_HI));
#pragma unroll
        for (int ntp = 0; ntp < 4; ++ntp) {
            uint32_t bh[4], bl[4];
            uint32_t baddr = sb + H_HI + swz(cb_row, (uint32_t)(dh * 8 + ntp * 2) + cb_gh);
            ldsm4t(bh, baddr);
            ldsm4t(bl, baddr + (H_LO - H_HI));
#pragma unroll
            for (int j = 0; j < 2; ++j) {
                mma_bf16(cacc[ntp * 2 + j], uhf, bh + 2 * j);
                mma_bf16(cacc[ntp * 2 + j], uhf, bl + 2 * j);
                mma_bf16(cacc[ntp * 2 + j], ulf, bh + 2 * j);
            }
        }
    }

    // ---- write partials ----
    {
        float* part = g_part + (size_t)(b * S_CHUNKS + chunk) * (QN * DN);
        const int q1 = qg * 16 + (lane >> 2), q2 = q1 + 8;
#pragma unroll
        for (int nt = 0; nt < 8; ++nt) {
            int d0 = dh * 64 + (nt >> 1) * 16 + (nt & 1) * 8 + (lane & 3) * 2;
            *reinterpret_cast<float2*>(part + q1 * DN + d0) =
                make_float2(cacc[nt][0], cacc[nt][1]);
            *reinterpret_cast<float2*>(part + q2 * DN + d0) =
                make_float2(cacc[nt][2], cacc[nt][3]);
        }
    }
}

// ---------------------------------------------------------------------------
// out = sum over chunks of g_part.  Pure float4 stream.
// ---------------------------------------------------------------------------
__global__ __launch_bounds__(256) void red_kernel(float* __restrict__ out)
{
    int i4 = blockIdx.x * 256 + threadIdx.x;   // 0 .. 65535
    int b = i4 >> 11;                          // QN*DN/4 = 2048 float4 per b
    int qd4 = i4 & 2047;
    const float4* p4 = reinterpret_cast<const float4*>(g_part);
    float4 v = make_float4(0.f, 0.f, 0.f, 0.f);
    size_t base = (size_t)b * S_CHUNKS * 2048 + qd4;
#pragma unroll
    for (int ch = 0; ch < S_CHUNKS; ++ch) {
        float4 w = p4[base + (size_t)ch * 2048];
        v.x += w.x; v.y += w.y; v.z += w.z; v.w += w.w;
    }
    reinterpret_cast<float4*>(out)[i4] = v;
}

// ---------------------------------------------------------------------------
extern "C" void kernel_launch(void* const* d_in, const int* in_sizes, int n_in,
                              void* d_out, int out_size)
{
    (void)in_sizes; (void)n_in; (void)out_size;
    const float* story_a = (const float*)d_in[0];
    const float* u       = (const float*)d_in[1];
    const float* story_c = (const float*)d_in[2];
    const float* H       = (const float*)d_in[3];
    float* out = (float*)d_out;

    cudaFuncSetAttribute(attn_mma, cudaFuncAttributeMaxDynamicSharedMemorySize, SMEM_TOTAL);
    dim3 grid(S_CHUNKS, B_);
    attn_mma<<<grid, THREADS, SMEM_TOTAL>>>(story_a, u, story_c, H);

    red_kernel<<<B_ * QN * DN / 1024, 256>>>(out);
}

// round 14
// speedup vs baseline: 1.1040x; 1.1040x over previous
#include <cuda_runtime.h>
#include <cuda_bf16.h>
#include <cuda_fp16.h>
#include <cstdint>

#define B_ 32
#define M_ 8192
#define QN 64
#define DN 128
#define S_CHUNKS 8
#define CHUNK 1024
#define MT 64
#define NT 16
#define THREADS 256

#define ROW  256   // A/C/U row bytes (128 elems x 2B), XOR-swizzled 16B granules
#define PROW 128   // P row bytes (64 elems x 2B)

// shared memory byte offsets (99328 B -> 2 CTAs/SM)
#define A_HI 0
#define A_LO 16384
#define C_F  32768
#define U_HI 49152
#define U_LO 65536
#define P_HI 81920
#define P_LO 90112
#define RED_OFF 98304
#define SMEM_TOTAL (98304 + 1024)

// partial sums: [b*S_CHUNKS+chunk][q*DN+d]  (8.4 MB)
__device__ float g_part[(size_t)B_ * S_CHUNKS * QN * DN];

__device__ __forceinline__ uint32_t smem_u32(const void* p) {
    uint32_t a;
    asm("{ .reg .u64 t; cvta.to.shared.u64 t, %1; cvt.u32.u64 %0, t; }" : "=r"(a) : "l"(p));
    return a;
}
__device__ __forceinline__ uint32_t swz(uint32_t r, uint32_t g) {
    return r * ROW + ((g ^ (r & 7)) << 4);
}
__device__ __forceinline__ uint32_t swzp(uint32_t r, uint32_t g) {
    return r * PROW + ((g ^ (r & 7)) << 4);
}
__device__ __forceinline__ void ldsm4(uint32_t* r, uint32_t a) {
    asm volatile("ldmatrix.sync.aligned.m8n8.x4.shared.b16 {%0,%1,%2,%3}, [%4];"
                 : "=r"(r[0]), "=r"(r[1]), "=r"(r[2]), "=r"(r[3]) : "r"(a));
}
__device__ __forceinline__ void ldsm4t(uint32_t* r, uint32_t a) {
    asm volatile("ldmatrix.sync.aligned.m8n8.x4.trans.shared.b16 {%0,%1,%2,%3}, [%4];"
                 : "=r"(r[0]), "=r"(r[1]), "=r"(r[2]), "=r"(r[3]) : "r"(a));
}
__device__ __forceinline__ void mma_bf16(float* d, const uint32_t* a, const uint32_t* b) {
    asm volatile(
        "mma.sync.aligned.m16n8k16.row.col.f32.bf16.bf16.f32 "
        "{%0,%1,%2,%3}, {%4,%5,%6,%7}, {%8,%9}, {%0,%1,%2,%3};"
        : "+f"(d[0]), "+f"(d[1]), "+f"(d[2]), "+f"(d[3])
        : "r"(a[0]), "r"(a[1]), "r"(a[2]), "r"(a[3]), "r"(b[0]), "r"(b[1]));
}
__device__ __forceinline__ void mma_f16(float* d, const uint32_t* a, const uint32_t* b) {
    asm volatile(
        "mma.sync.aligned.m16n8k16.row.col.f32.f16.f16.f32 "
        "{%0,%1,%2,%3}, {%4,%5,%6,%7}, {%8,%9}, {%0,%1,%2,%3};"
        : "+f"(d[0]), "+f"(d[1]), "+f"(d[2]), "+f"(d[3])
        : "r"(a[0]), "r"(a[1]), "r"(a[2]), "r"(a[3]), "r"(b[0]), "r"(b[1]));
}
// bf16 hi/lo split (packed pairs)
__device__ __forceinline__ void cvt2(float x0, float x1, uint32_t& hi, uint32_t& lo) {
    __nv_bfloat162 h = __float22bfloat162_rn(make_float2(x0, x1));
    hi = *reinterpret_cast<uint32_t*>(&h);
    float h0 = __uint_as_float(hi << 16);
    float h1 = __uint_as_float(hi & 0xFFFF0000u);
    __nv_bfloat162 l = __float22bfloat162_rn(make_float2(x0 - h0, x1 - h1));
    lo = *reinterpret_cast<uint32_t*>(&l);
}
// fp16 single pack
__device__ __forceinline__ uint32_t cvth(float x0, float x1) {
    __half2 h = __float22half2_rn(make_float2(x0, x1));
    return *reinterpret_cast<uint32_t*>(&h);
}
// fp16 hi/lo split (packed pairs)
__device__ __forceinline__ void cvt2h(float x0, float x1, uint32_t& hi, uint32_t& lo) {
    __half2 h = __float22half2_rn(make_float2(x0, x1));
    hi = *reinterpret_cast<uint32_t*>(&h);
    float h0 = __half2float(__low2half(h));
    float h1 = __half2float(__high2half(h));
    __half2 l = __float22half2_rn(make_float2(x0 - h0, x1 - h1));
    lo = *reinterpret_cast<uint32_t*>(&l);
}

// ---------------------------------------------------------------------------
__global__ __launch_bounds__(THREADS, 2) void attn_mma(
    const float* __restrict__ story_a, const float* __restrict__ u,
    const float* __restrict__ story_c)
{
    extern __shared__ char sm[];
    const uint32_t sb = smem_u32(sm);
    float2* red = reinterpret_cast<float2*>(sm + RED_OFF);   // [row][qh]
    const int tid = threadIdx.x, lane = tid & 31, wid = tid >> 5;
    const int b = blockIdx.y, chunk = blockIdx.x;
    const int m_base_g = chunk * CHUNK;

    // ---- stage u (64q x 128d), bf16 hi/lo, swizzled ----
    {
        const float4* g4 = reinterpret_cast<const float4*>(u + (size_t)b * QN * DN);
        for (int i = tid; i < QN * DN / 4; i += THREADS) {
            int q = i >> 5, j = i & 31;
            float4 v = g4[i];
            uint32_t h0, l0, h1, l1;
            cvt2(v.x, v.y, h0, l0); cvt2(v.z, v.w, h1, l1);
            uint32_t off = swz(q, j >> 1) + (j & 1) * 8;
            *reinterpret_cast<uint2*>(sm + U_HI + off) = make_uint2(h0, h1);
            *reinterpret_cast<uint2*>(sm + U_LO + off) = make_uint2(l0, l1);
        }
    }

    // GEMM1: warp = 16m x 32q.
    const int mg = wid & 3, qh = wid >> 2;
    const uint32_t a1_row = (uint32_t)(mg * 16 + (lane & 15));
    const uint32_t a1_gh  = (lane & 16) ? 1u : 0u;
    const uint32_t b1_row = (uint32_t)((lane & 7) + ((lane & 16) ? 8 : 0));
    const uint32_t b1_gh  = (lane & 8) ? 1u : 0u;
    // GEMM2: warp = 16q x 64d.
    const int qg = wid & 3, dh = wid >> 5 == 0 ? (wid >> 2) : (wid >> 2);
    const uint32_t pa_row = (uint32_t)((lane & 7) + ((lane & 16) ? 8 : 0));
    const uint32_t pa_g   = (uint32_t)(qg * 2 + ((lane & 8) ? 1 : 0));
    const uint32_t cb_row = (uint32_t)((lane & 7) + ((lane & 8) ? 8 : 0));
    const uint32_t cb_gh  = (lane & 16) ? 1u : 0u;

    float cacc[8][4];
#pragma unroll
    for (int i = 0; i < 8; ++i)
#pragma unroll
        for (int j = 0; j < 4; ++j) cacc[i][j] = 0.f;

    for (int t = 0; t < NT; ++t) {
        // ---- prefetch story_a tile into registers BEFORE the barrier ----
        const float4* ga = reinterpret_cast<const float4*>(
            story_a + ((size_t)b * M_ + m_base_g + t * MT) * DN);
        const float4* gc = reinterpret_cast<const float4*>(
            story_c + ((size_t)b * M_ + m_base_g + t * MT) * DN);
        float4 a_pre[8];
#pragma unroll
        for (int k = 0; k < 8; ++k) a_pre[k] = ga[tid + k * THREADS];

        __syncthreads();   // previous tile fully consumed

        // ---- issue story_c loads, then convert+store A (hides C latency) ----
        {
            float4 c_pre[8];
#pragma unroll
            for (int k = 0; k < 8; ++k) c_pre[k] = gc[tid + k * THREADS];
#pragma unroll
            for (int k = 0; k < 8; ++k) {
                int i = tid + k * THREADS;
                int m = i >> 5, j = i & 31;
                uint32_t off = swz(m, j >> 1) + (j & 1) * 8;
                uint32_t h0, l0, h1, l1;
                cvt2(a_pre[k].x, a_pre[k].y, h0, l0);
                cvt2(a_pre[k].z, a_pre[k].w, h1, l1);
                *reinterpret_cast<uint2*>(sm + A_HI + off) = make_uint2(h0, h1);
                *reinterpret_cast<uint2*>(sm + A_LO + off) = make_uint2(l0, l1);
            }
#pragma unroll
            for (int k = 0; k < 8; ++k) {
                int i = tid + k * THREADS;
                int m = i >> 5, j = i & 31;
                uint32_t off = swz(m, j >> 1) + (j & 1) * 8;
                *reinterpret_cast<uint2*>(sm + C_F + off) =
                    make_uint2(cvth(c_pre[k].x, c_pre[k].y), cvth(c_pre[k].z, c_pre[k].w));
            }
        }
        __syncthreads();

        // ---- GEMM1: S[16m][32q], bf16 3-pass, K=128, A-frag double-buffered ----
        float s[4][4];
#pragma unroll
        for (int i = 0; i < 4; ++i)
#pragma unroll
            for (int j = 0; j < 4; ++j) s[i][j] = 0.f;

        uint32_t ahb[2][4], alb[2][4];
        {
            uint32_t a0 = sb + A_HI + swz(a1_row, a1_gh);
            ldsm4(ahb[0], a0);
            ldsm4(alb[0], a0 + (A_LO - A_HI));
        }
#pragma unroll
        for (int ks = 0; ks < 8; ++ks) {
            const int cur = ks & 1, nxt = cur ^ 1;
            if (ks < 7) {
                uint32_t an = sb + A_HI + swz(a1_row, (uint32_t)(ks + 1) * 2 + a1_gh);
                ldsm4(ahb[nxt], an);
                ldsm4(alb[nxt], an + (A_LO - A_HI));
            }
#pragma unroll
            for (int ntp = 0; ntp < 2; ++ntp) {
                uint32_t bh[4], bl[4];
                uint32_t baddr = sb + U_HI
                    + swz((uint32_t)(qh * 32 + ntp * 16) + b1_row, (uint32_t)ks * 2 + b1_gh);
                ldsm4(bh, baddr);
                ldsm4(bl, baddr + (U_LO - U_HI));
#pragma unroll
                for (int j = 0; j < 2; ++j) {
                    mma_bf16(s[ntp * 2 + j], ahb[cur], bh + 2 * j);
                    mma_bf16(s[ntp * 2 + j], ahb[cur], bl + 2 * j);
                    mma_bf16(s[ntp * 2 + j], alb[cur], bh + 2 * j);
                }
            }
        }

        // ---- softmax over q: local stats + one-barrier cross-half merge ----
        {
            const uint32_t r1 = (uint32_t)(mg * 16 + (lane >> 2)), r2 = r1 + 8;
            float mx1 = -1e30f, mx2 = -1e30f;
#pragma unroll
            for (int nt = 0; nt < 4; ++nt) {
                mx1 = fmaxf(mx1, fmaxf(s[nt][0], s[nt][1]));
                mx2 = fmaxf(mx2, fmaxf(s[nt][2], s[nt][3]));
            }
            mx1 = fmaxf(mx1, __shfl_xor_sync(0xffffffffu, mx1, 1));
            mx1 = fmaxf(mx1, __shfl_xor_sync(0xffffffffu, mx1, 2));
            mx2 = fmaxf(mx2, __shfl_xor_sync(0xffffffffu, mx2, 1));
            mx2 = fmaxf(mx2, __shfl_xor_sync(0xffffffffu, mx2, 2));
            float sum1 = 0.f, sum2 = 0.f;
#pragma unroll
            for (int nt = 0; nt < 4; ++nt) {
                s[nt][0] = __expf(s[nt][0] - mx1); sum1 += s[nt][0];
                s[nt][1] = __expf(s[nt][1] - mx1); sum1 += s[nt][1];
                s[nt][2] = __expf(s[nt][2] - mx2); sum2 += s[nt][2];
                s[nt][3] = __expf(s[nt][3] - mx2); sum2 += s[nt][3];
            }
            sum1 += __shfl_xor_sync(0xffffffffu, sum1, 1);
            sum1 += __shfl_xor_sync(0xffffffffu, sum1, 2);
            sum2 += __shfl_xor_sync(0xffffffffu, sum2, 1);
            sum2 += __shfl_xor_sync(0xffffffffu, sum2, 2);
            if ((lane & 3) == 0) {
                red[r1 * 2 + qh] = make_float2(mx1, sum1);
                red[r2 * 2 + qh] = make_float2(mx2, sum2);
            }
            __syncthreads();
            float2 o1 = red[r1 * 2 + (1 - qh)];
            float2 o2 = red[r2 * 2 + (1 - qh)];
            float g1 = fmaxf(mx1, o1.x), g2 = fmaxf(mx2, o2.x);
            float e1 = __expf(mx1 - g1), e2 = __expf(mx2 - g2);
            float f1 = e1 / (sum1 * e1 + o1.y * __expf(o1.x - g1));
            float f2 = e2 / (sum2 * e2 + o2.y * __expf(o2.x - g2));

            const uint32_t qb = (uint32_t)(lane & 3) * 4;
#pragma unroll
            for (int nt = 0; nt < 4; ++nt) {
                uint32_t h, l;
                uint32_t g = (uint32_t)(qh * 4 + nt);
                uint32_t o1b = swzp(r1, g) + qb;
                uint32_t o2b = swzp(r2, g) + qb;
                cvt2h(s[nt][0] * f1, s[nt][1] * f1, h, l);
                *reinterpret_cast<uint32_t*>(sm + P_HI + o1b) = h;
                *reinterpret_cast<uint32_t*>(sm + P_LO + o1b) = l;
                cvt2h(s[nt][2] * f2, s[nt][3] * f2, h, l);
                *reinterpret_cast<uint32_t*>(sm + P_HI + o2b) = h;
                *reinterpret_cast<uint32_t*>(sm + P_LO + o2b) = l;
            }
        }
        __syncthreads();

        // ---- GEMM2: C[16q][64d] += P^T * SC, fp16 2-pass, K=64 ----
        uint32_t phb[2][4], plb[2][4];
        {
            uint32_t p0 = sb + P_HI + swzp(pa_row, pa_g);
            ldsm4t(phb[0], p0);
            ldsm4t(plb[0], p0 + (P_LO - P_HI));
        }
#pragma unroll
        for (int ks = 0; ks < 4; ++ks) {
            const int cur = ks & 1, nxt = cur ^ 1;
            if (ks < 3) {
                uint32_t pn = sb + P_HI + swzp((uint32_t)(ks + 1) * 16 + pa_row, pa_g);
                ldsm4t(phb[nxt], pn);
                ldsm4t(plb[nxt], pn + (P_LO - P_HI));
            }
#pragma unroll
            for (int ntp = 0; ntp < 4; ++ntp) {
                uint32_t bf[4];
                uint32_t baddr = sb + C_F
                    + swz((uint32_t)ks * 16 + cb_row, (uint32_t)(dh * 8 + ntp * 2) + cb_gh);
                ldsm4t(bf, baddr);
#pragma unroll
                for (int j = 0; j < 2; ++j) {
                    mma_f16(cacc[ntp * 2 + j], phb[cur], bf + 2 * j);
                    mma_f16(cacc[ntp * 2 + j], plb[cur], bf + 2 * j);
                }
            }
        }
    }

    // ---- write partials ----
    {
        float* part = g_part + (size_t)(b * S_CHUNKS + chunk) * (QN * DN);
        const int q1 = qg * 16 + (lane >> 2), q2 = q1 + 8;
#pragma unroll
        for (int nt = 0; nt < 8; ++nt) {
            int d0 = dh * 64 + (nt >> 1) * 16 + (nt & 1) * 8 + (lane & 3) * 2;
            *reinterpret_cast<float2*>(part + q1 * DN + d0) =
                make_float2(cacc[nt][0], cacc[nt][1]);
            *reinterpret_cast<float2*>(part + q2 * DN + d0) =
                make_float2(cacc[nt][2], cacc[nt][3]);
        }
    }
}

// ---------------------------------------------------------------------------
// out[b,q,:] = u[b,q,:] @ H + sum_ch g_part[b,ch,q,:]
// 256 CTAs x 256 thr; warp = one (b,q) row. H + 8 u-rows staged in smem.
// Partial-sum LDGs issued before the barrier; consumed after the FFMA loop.
// ---------------------------------------------------------------------------
#define OUT_SMEM ((DN * DN + 8 * DN) * 4)   // 69632
__global__ __launch_bounds__(256) void out_kernel(
    const float* __restrict__ u, const float* __restrict__ H, float* __restrict__ out)
{
    extern __shared__ float sh[];
    float* Hs = sh;              // 128 x 128
    float* us = sh + DN * DN;    // 8 x 128
    const int blk = blockIdx.x, tid = threadIdx.x;
    const int lane = tid & 31, wid = tid >> 5;

    {
        const float4* H4 = reinterpret_cast<const float4*>(H);
        float4* Hs4 = reinterpret_cast<float4*>(Hs);
#pragma unroll
        for (int i = 0; i < 16; ++i) Hs4[tid + i * 256] = H4[tid + i * 256];
        const float4* u4 = reinterpret_cast<const float4*>(u + (size_t)blk * 8 * DN);
        reinterpret_cast<float4*>(us)[tid] = u4[tid];
    }

    // issue partial-sum loads early (independent of smem)
    const int row = blk * 8 + wid;            // global (b,q) row
    const int b = row >> 6, q = row & 63;
    const float4* p4 = reinterpret_cast<const float4*>(g_part);
    const size_t base = (size_t)b * S_CHUNKS * 2048 + (size_t)q * 32 + lane;
    float4 pr[S_CHUNKS];
#pragma unroll
    for (int ch = 0; ch < S_CHUNKS; ++ch)
        pr[ch] = p4[base + (size_t)ch * 2048];

    __syncthreads();

    const float4* Hs4 = reinterpret_cast<const float4*>(Hs);
    const float* up = us + wid * DN;
    float4 acc = make_float4(0.f, 0.f, 0.f, 0.f);
#pragma unroll 16
    for (int e = 0; e < DN; ++e) {
        float4 h = Hs4[e * 32 + lane];
        float x = up[e];
        acc.x += x * h.x; acc.y += x * h.y; acc.z += x * h.z; acc.w += x * h.w;
    }
#pragma unroll
    for (int ch = 0; ch < S_CHUNKS; ++ch) {
        acc.x += pr[ch].x; acc.y += pr[ch].y;
        acc.z += pr[ch].z; acc.w += pr[ch].w;
    }
    reinterpret_cast<float4*>(out)[(size_t)row * 32 + lane] = acc;
}

// ---------------------------------------------------------------------------
extern "C" void kernel_launch(void* const* d_in, const int* in_sizes, int n_in,
                              void* d_out, int out_size)
{
    (void)in_sizes; (void)n_in; (void)out_size;
    const float* story_a = (const float*)d_in[0];
    const float* u       = (const float*)d_in[1];
    const float* story_c = (const float*)d_in[2];
    const float* H       = (const float*)d_in[3];
    float* out = (float*)d_out;

    cudaFuncSetAttribute(attn_mma, cudaFuncAttributeMaxDynamicSharedMemorySize, SMEM_TOTAL);
    dim3 grid(S_CHUNKS, B_);
    attn_mma<<<grid, THREADS, SMEM_TOTAL>>>(story_a, u, story_c);

    cudaFuncSetAttribute(out_kernel, cudaFuncAttributeMaxDynamicSharedMemorySize, OUT_SMEM);
    out_kernel<<<B_ * QN / 8, 256, OUT_SMEM>>>(u, H, out);
}

// round 15
// speedup vs baseline: 1.1759x; 1.0652x over previous
#include <cuda_runtime.h>
#include <cuda_bf16.h>
#include <cuda_fp16.h>
#include <cstdint>

#define B_ 32
#define M_ 8192
#define QN 64
#define DN 128
#define S_CHUNKS 8
#define CHUNK 1024
#define MT 64
#define NT 16
#define THREADS 256

#define ROW  256   // A/C/U row bytes (128 elems x 2B), XOR-swizzled 16B granules
#define PROW 128   // P row bytes (64 elems x 2B)

// shared memory byte offsets (91136 B -> 2 CTAs/SM)
#define A_HI 0
#define A_LO 16384
#define C_F  32768
#define U_HI 49152
#define U_LO 65536
#define P_F  81920
#define RED_OFF 90112
#define SMEM_TOTAL (90112 + 1024)

// partial sums: [b*S_CHUNKS+chunk][q*DN+d]  (8.4 MB)
__device__ float g_part[(size_t)B_ * S_CHUNKS * QN * DN];

__device__ __forceinline__ uint32_t smem_u32(const void* p) {
    uint32_t a;
    asm("{ .reg .u64 t; cvta.to.shared.u64 t, %1; cvt.u32.u64 %0, t; }" : "=r"(a) : "l"(p));
    return a;
}
__device__ __forceinline__ uint32_t swz(uint32_t r, uint32_t g) {
    return r * ROW + ((g ^ (r & 7)) << 4);
}
__device__ __forceinline__ uint32_t swzp(uint32_t r, uint32_t g) {
    return r * PROW + ((g ^ (r & 7)) << 4);
}
__device__ __forceinline__ void ldsm4(uint32_t* r, uint32_t a) {
    asm volatile("ldmatrix.sync.aligned.m8n8.x4.shared.b16 {%0,%1,%2,%3}, [%4];"
                 : "=r"(r[0]), "=r"(r[1]), "=r"(r[2]), "=r"(r[3]) : "r"(a));
}
__device__ __forceinline__ void ldsm4t(uint32_t* r, uint32_t a) {
    asm volatile("ldmatrix.sync.aligned.m8n8.x4.trans.shared.b16 {%0,%1,%2,%3}, [%4];"
                 : "=r"(r[0]), "=r"(r[1]), "=r"(r[2]), "=r"(r[3]) : "r"(a));
}
__device__ __forceinline__ void mma_bf16(float* d, const uint32_t* a, const uint32_t* b) {
    asm volatile(
        "mma.sync.aligned.m16n8k16.row.col.f32.bf16.bf16.f32 "
        "{%0,%1,%2,%3}, {%4,%5,%6,%7}, {%8,%9}, {%0,%1,%2,%3};"
        : "+f"(d[0]), "+f"(d[1]), "+f"(d[2]), "+f"(d[3])
        : "r"(a[0]), "r"(a[1]), "r"(a[2]), "r"(a[3]), "r"(b[0]), "r"(b[1]));
}
__device__ __forceinline__ void mma_f16(float* d, const uint32_t* a, const uint32_t* b) {
    asm volatile(
        "mma.sync.aligned.m16n8k16.row.col.f32.f16.f16.f32 "
        "{%0,%1,%2,%3}, {%4,%5,%6,%7}, {%8,%9}, {%0,%1,%2,%3};"
        : "+f"(d[0]), "+f"(d[1]), "+f"(d[2]), "+f"(d[3])
        : "r"(a[0]), "r"(a[1]), "r"(a[2]), "r"(a[3]), "r"(b[0]), "r"(b[1]));
}
// bf16 hi/lo split (packed pairs)
__device__ __forceinline__ void cvt2(float x0, float x1, uint32_t& hi, uint32_t& lo) {
    __nv_bfloat162 h = __float22bfloat162_rn(make_float2(x0, x1));
    hi = *reinterpret_cast<uint32_t*>(&h);
    float h0 = __uint_as_float(hi << 16);
    float h1 = __uint_as_float(hi & 0xFFFF0000u);
    __nv_bfloat162 l = __float22bfloat162_rn(make_float2(x0 - h0, x1 - h1));
    lo = *reinterpret_cast<uint32_t*>(&l);
}
// fp16 single pack
__device__ __forceinline__ uint32_t cvth(float x0, float x1) {
    __half2 h = __float22half2_rn(make_float2(x0, x1));
    return *reinterpret_cast<uint32_t*>(&h);
}

// ---------------------------------------------------------------------------
__global__ __launch_bounds__(THREADS, 2) void attn_mma(
    const float* __restrict__ story_a, const float* __restrict__ u,
    const float* __restrict__ story_c)
{
    extern __shared__ char sm[];
    const uint32_t sb = smem_u32(sm);
    float2* red = reinterpret_cast<float2*>(sm + RED_OFF);   // [row][qh]
    const int tid = threadIdx.x, lane = tid & 31, wid = tid >> 5;
    const int b = blockIdx.y, chunk = blockIdx.x;
    const int m_base_g = chunk * CHUNK;

    // ---- stage u (64q x 128d), bf16 hi/lo, swizzled ----
    {
        const float4* g4 = reinterpret_cast<const float4*>(u + (size_t)b * QN * DN);
        for (int i = tid; i < QN * DN / 4; i += THREADS) {
            int q = i >> 5, j = i & 31;
            float4 v = g4[i];
            uint32_t h0, l0, h1, l1;
            cvt2(v.x, v.y, h0, l0); cvt2(v.z, v.w, h1, l1);
            uint32_t off = swz(q, j >> 1) + (j & 1) * 8;
            *reinterpret_cast<uint2*>(sm + U_HI + off) = make_uint2(h0, h1);
            *reinterpret_cast<uint2*>(sm + U_LO + off) = make_uint2(l0, l1);
        }
    }

    // GEMM1: warp = 16m x 32q.
    const int mg = wid & 3, qh = wid >> 2;
    const uint32_t a1_row = (uint32_t)(mg * 16 + (lane & 15));
    const uint32_t a1_gh  = (lane & 16) ? 1u : 0u;
    const uint32_t b1_row = (uint32_t)((lane & 7) + ((lane & 16) ? 8 : 0));
    const uint32_t b1_gh  = (lane & 8) ? 1u : 0u;
    // GEMM2: warp = 16q x 64d.
    const int qg = wid & 3, dh = wid >> 2;
    const uint32_t pa_row = (uint32_t)((lane & 7) + ((lane & 16) ? 8 : 0));
    const uint32_t pa_g   = (uint32_t)(qg * 2 + ((lane & 8) ? 1 : 0));
    const uint32_t cb_row = (uint32_t)((lane & 7) + ((lane & 8) ? 8 : 0));
    const uint32_t cb_gh  = (lane & 16) ? 1u : 0u;

    float cacc[8][4];
#pragma unroll
    for (int i = 0; i < 8; ++i)
#pragma unroll
        for (int j = 0; j < 4; ++j) cacc[i][j] = 0.f;

    for (int t = 0; t < NT; ++t) {
        // ---- prefetch story_a tile into registers BEFORE the barrier ----
        const float4* ga = reinterpret_cast<const float4*>(
            story_a + ((size_t)b * M_ + m_base_g + t * MT) * DN);
        const float4* gc = reinterpret_cast<const float4*>(
            story_c + ((size_t)b * M_ + m_base_g + t * MT) * DN);
        float4 a_pre[8];
#pragma unroll
        for (int k = 0; k < 8; ++k) a_pre[k] = ga[tid + k * THREADS];

        __syncthreads();   // previous tile fully consumed

        // ---- issue story_c loads, then convert+store A (hides C latency) ----
        {
            float4 c_pre[8];
#pragma unroll
            for (int k = 0; k < 8; ++k) c_pre[k] = gc[tid + k * THREADS];
#pragma unroll
            for (int k = 0; k < 8; ++k) {
                int i = tid + k * THREADS;
                int m = i >> 5, j = i & 31;
                uint32_t off = swz(m, j >> 1) + (j & 1) * 8;
                uint32_t h0, l0, h1, l1;
                cvt2(a_pre[k].x, a_pre[k].y, h0, l0);
                cvt2(a_pre[k].z, a_pre[k].w, h1, l1);
                *reinterpret_cast<uint2*>(sm + A_HI + off) = make_uint2(h0, h1);
                *reinterpret_cast<uint2*>(sm + A_LO + off) = make_uint2(l0, l1);
            }
#pragma unroll
            for (int k = 0; k < 8; ++k) {
                int i = tid + k * THREADS;
                int m = i >> 5, j = i & 31;
                uint32_t off = swz(m, j >> 1) + (j & 1) * 8;
                *reinterpret_cast<uint2*>(sm + C_F + off) =
                    make_uint2(cvth(c_pre[k].x, c_pre[k].y), cvth(c_pre[k].z, c_pre[k].w));
            }
        }
        __syncthreads();

        // ---- GEMM1: S[16m][32q], bf16 3-pass, K=128, A-frag double-buffered ----
        float s[4][4];
#pragma unroll
        for (int i = 0; i < 4; ++i)
#pragma unroll
            for (int j = 0; j < 4; ++j) s[i][j] = 0.f;

        uint32_t ahb[2][4], alb[2][4];
        {
            uint32_t a0 = sb + A_HI + swz(a1_row, a1_gh);
            ldsm4(ahb[0], a0);
            ldsm4(alb[0], a0 + (A_LO - A_HI));
        }
#pragma unroll
        for (int ks = 0; ks < 8; ++ks) {
            const int cur = ks & 1, nxt = cur ^ 1;
            if (ks < 7) {
                uint32_t an = sb + A_HI + swz(a1_row, (uint32_t)(ks + 1) * 2 + a1_gh);
                ldsm4(ahb[nxt], an);
                ldsm4(alb[nxt], an + (A_LO - A_HI));
            }
#pragma unroll
            for (int ntp = 0; ntp < 2; ++ntp) {
                uint32_t bh[4], bl[4];
                uint32_t baddr = sb + U_HI
                    + swz((uint32_t)(qh * 32 + ntp * 16) + b1_row, (uint32_t)ks * 2 + b1_gh);
                ldsm4(bh, baddr);
                ldsm4(bl, baddr + (U_LO - U_HI));
#pragma unroll
                for (int j = 0; j < 2; ++j) {
                    mma_bf16(s[ntp * 2 + j], ahb[cur], bh + 2 * j);
                    mma_bf16(s[ntp * 2 + j], ahb[cur], bl + 2 * j);
                    mma_bf16(s[ntp * 2 + j], alb[cur], bh + 2 * j);
                }
            }
        }

        // ---- softmax over q: local stats + one-barrier cross-half merge ----
        {
            const uint32_t r1 = (uint32_t)(mg * 16 + (lane >> 2)), r2 = r1 + 8;
            float mx1 = -1e30f, mx2 = -1e30f;
#pragma unroll
            for (int nt = 0; nt < 4; ++nt) {
                mx1 = fmaxf(mx1, fmaxf(s[nt][0], s[nt][1]));
                mx2 = fmaxf(mx2, fmaxf(s[nt][2], s[nt][3]));
            }
            mx1 = fmaxf(mx1, __shfl_xor_sync(0xffffffffu, mx1, 1));
            mx1 = fmaxf(mx1, __shfl_xor_sync(0xffffffffu, mx1, 2));
            mx2 = fmaxf(mx2, __shfl_xor_sync(0xffffffffu, mx2, 1));
            mx2 = fmaxf(mx2, __shfl_xor_sync(0xffffffffu, mx2, 2));
            float sum1 = 0.f, sum2 = 0.f;
#pragma unroll
            for (int nt = 0; nt < 4; ++nt) {
                s[nt][0] = __expf(s[nt][0] - mx1); sum1 += s[nt][0];
                s[nt][1] = __expf(s[nt][1] - mx1); sum1 += s[nt][1];
                s[nt][2] = __expf(s[nt][2] - mx2); sum2 += s[nt][2];
                s[nt][3] = __expf(s[nt][3] - mx2); sum2 += s[nt][3];
            }
            sum1 += __shfl_xor_sync(0xffffffffu, sum1, 1);
            sum1 += __shfl_xor_sync(0xffffffffu, sum1, 2);
            sum2 += __shfl_xor_sync(0xffffffffu, sum2, 1);
            sum2 += __shfl_xor_sync(0xffffffffu, sum2, 2);
            if ((lane & 3) == 0) {
                red[r1 * 2 + qh] = make_float2(mx1, sum1);
                red[r2 * 2 + qh] = make_float2(mx2, sum2);
            }
            __syncthreads();
            float2 o1 = red[r1 * 2 + (1 - qh)];
            float2 o2 = red[r2 * 2 + (1 - qh)];
            float g1 = fmaxf(mx1, o1.x), g2 = fmaxf(mx2, o2.x);
            float e1 = __expf(mx1 - g1), e2 = __expf(mx2 - g2);
            float f1 = e1 / (sum1 * e1 + o1.y * __expf(o1.x - g1));
            float f2 = e2 / (sum2 * e2 + o2.y * __expf(o2.x - g2));

            const uint32_t qb = (uint32_t)(lane & 3) * 4;
#pragma unroll
            for (int nt = 0; nt < 4; ++nt) {
                uint32_t g = (uint32_t)(qh * 4 + nt);
                uint32_t o1b = swzp(r1, g) + qb;
                uint32_t o2b = swzp(r2, g) + qb;
                *reinterpret_cast<uint32_t*>(sm + P_F + o1b) =
                    cvth(s[nt][0] * f1, s[nt][1] * f1);
                *reinterpret_cast<uint32_t*>(sm + P_F + o2b) =
                    cvth(s[nt][2] * f2, s[nt][3] * f2);
            }
        }
        __syncthreads();

        // ---- GEMM2: C[16q][64d] += P^T * SC, fp16 SINGLE-pass, K=64 ----
        uint32_t phb[2][4];
        {
            uint32_t p0 = sb + P_F + swzp(pa_row, pa_g);
            ldsm4t(phb[0], p0);
        }
#pragma unroll
        for (int ks = 0; ks < 4; ++ks) {
            const int cur = ks & 1, nxt = cur ^ 1;
            if (ks < 3) {
                uint32_t pn = sb + P_F + swzp((uint32_t)(ks + 1) * 16 + pa_row, pa_g);
                ldsm4t(phb[nxt], pn);
            }
#pragma unroll
            for (int ntp = 0; ntp < 4; ++ntp) {
                uint32_t bf[4];
                uint32_t baddr = sb + C_F
                    + swz((uint32_t)ks * 16 + cb_row, (uint32_t)(dh * 8 + ntp * 2) + cb_gh);
                ldsm4t(bf, baddr);
#pragma unroll
                for (int j = 0; j < 2; ++j)
                    mma_f16(cacc[ntp * 2 + j], phb[cur], bf + 2 * j);
            }
        }
    }

    // ---- write partials ----
    {
        float* part = g_part + (size_t)(b * S_CHUNKS + chunk) * (QN * DN);
        const int q1 = qg * 16 + (lane >> 2), q2 = q1 + 8;
#pragma unroll
        for (int nt = 0; nt < 8; ++nt) {
            int d0 = dh * 64 + (nt >> 1) * 16 + (nt & 1) * 8 + (lane & 3) * 2;
            *reinterpret_cast<float2*>(part + q1 * DN + d0) =
                make_float2(cacc[nt][0], cacc[nt][1]);
            *reinterpret_cast<float2*>(part + q2 * DN + d0) =
                make_float2(cacc[nt][2], cacc[nt][3]);
        }
    }
}

// ---------------------------------------------------------------------------
// out[b,q,:] = u[b,q,:] @ H + sum_ch g_part[b,ch,q,:]
// 256 CTAs x 256 thr; warp = one (b,q) row. H + 8 u-rows staged in smem.
// Partial-sum LDGs issued before the barrier; consumed after the FFMA loop.
// ---------------------------------------------------------------------------
#define OUT_SMEM ((DN * DN + 8 * DN) * 4)   // 69632
__global__ __launch_bounds__(256) void out_kernel(
    const float* __restrict__ u, const float* __restrict__ H, float* __restrict__ out)
{
    extern __shared__ float sh[];
    float* Hs = sh;              // 128 x 128
    float* us = sh + DN * DN;    // 8 x 128
    const int blk = blockIdx.x, tid = threadIdx.x;
    const int lane = tid & 31, wid = tid >> 5;

    {
        const float4* H4 = reinterpret_cast<const float4*>(H);
        float4* Hs4 = reinterpret_cast<float4*>(Hs);
#pragma unroll
        for (int i = 0; i < 16; ++i) Hs4[tid + i * 256] = H4[tid + i * 256];
        const float4* u4 = reinterpret_cast<const float4*>(u + (size_t)blk * 8 * DN);
        reinterpret_cast<float4*>(us)[tid] = u4[tid];
    }

    // issue partial-sum loads early (independent of smem)
    const int row = blk * 8 + wid;            // global (b,q) row
    const int b = row >> 6, q = row & 63;
    const float4* p4 = reinterpret_cast<const float4*>(g_part);
    const size_t base = (size_t)b * S_CHUNKS * 2048 + (size_t)q * 32 + lane;
    float4 pr[S_CHUNKS];
#pragma unroll
    for (int ch = 0; ch < S_CHUNKS; ++ch)
        pr[ch] = p4[base + (size_t)ch * 2048];

    __syncthreads();

    const float4* Hs4 = reinterpret_cast<const float4*>(Hs);
    const float* up = us + wid * DN;
    float4 acc = make_float4(0.f, 0.f, 0.f, 0.f);
#pragma unroll 16
    for (int e = 0; e < DN; ++e) {
        float4 h = Hs4[e * 32 + lane];
        float x = up[e];
        acc.x += x * h.x; acc.y += x * h.y; acc.z += x * h.z; acc.w += x * h.w;
    }
#pragma unroll
    for (int ch = 0; ch < S_CHUNKS; ++ch) {
        acc.x += pr[ch].x; acc.y += pr[ch].y;
        acc.z += pr[ch].z; acc.w += pr[ch].w;
    }
    reinterpret_cast<float4*>(out)[(size_t)row * 32 + lane] = acc;
}

// ---------------------------------------------------------------------------
extern "C" void kernel_launch(void* const* d_in, const int* in_sizes, int n_in,
                              void* d_out, int out_size)
{
    (void)in_sizes; (void)n_in; (void)out_size;
    const float* story_a = (const float*)d_in[0];
    const float* u       = (const float*)d_in[1];
    const float* story_c = (const float*)d_in[2];
    const float* H       = (const float*)d_in[3];
    float* out = (float*)d_out;

    cudaFuncSetAttribute(attn_mma, cudaFuncAttributeMaxDynamicSharedMemorySize, SMEM_TOTAL);
    dim3 grid(S_CHUNKS, B_);
    attn_mma<<<grid, THREADS, SMEM_TOTAL>>>(story_a, u, story_c);

    cudaFuncSetAttribute(out_kernel, cudaFuncAttributeMaxDynamicSharedMemorySize, OUT_SMEM);
    out_kernel<<<B_ * QN / 8, 256, OUT_SMEM>>>(u, H, out);
}

// round 16
// speedup vs baseline: 1.1824x; 1.0055x over previous
#include <cuda_runtime.h>
#include <cuda_bf16.h>
#include <cuda_fp16.h>
#include <cstdint>

#define B_ 32
#define M_ 8192
#define QN 64
#define DN 128
#define S_CHUNKS 8
#define CHUNK 1024
#define MT 64
#define NT 16
#define THREADS 256

#define ROW  256   // A/C/U row bytes (128 elems x 2B), XOR-swizzled 16B granules
#define PROW 128   // P row bytes (64 elems x 2B)

// shared memory byte offsets (91136 B -> 2 CTAs/SM)
#define A_HI 0
#define A_LO 16384
#define C_F  32768
#define U_HI 49152
#define U_LO 65536
#define P_F  81920
#define RED_OFF 90112
#define SMEM_TOTAL (90112 + 1024)

// partial sums: [b*S_CHUNKS+chunk][q*DN+d]  (8.4 MB)
__device__ float g_part[(size_t)B_ * S_CHUNKS * QN * DN];

__device__ __forceinline__ uint32_t smem_u32(const void* p) {
    uint32_t a;
    asm("{ .reg .u64 t; cvta.to.shared.u64 t, %1; cvt.u32.u64 %0, t; }" : "=r"(a) : "l"(p));
    return a;
}
__device__ __forceinline__ uint32_t swz(uint32_t r, uint32_t g) {
    return r * ROW + ((g ^ (r & 7)) << 4);
}
__device__ __forceinline__ uint32_t swzp(uint32_t r, uint32_t g) {
    return r * PROW + ((g ^ (r & 7)) << 4);
}
__device__ __forceinline__ void ldsm4(uint32_t* r, uint32_t a) {
    asm volatile("ldmatrix.sync.aligned.m8n8.x4.shared.b16 {%0,%1,%2,%3}, [%4];"
                 : "=r"(r[0]), "=r"(r[1]), "=r"(r[2]), "=r"(r[3]) : "r"(a));
}
__device__ __forceinline__ void ldsm4t(uint32_t* r, uint32_t a) {
    asm volatile("ldmatrix.sync.aligned.m8n8.x4.trans.shared.b16 {%0,%1,%2,%3}, [%4];"
                 : "=r"(r[0]), "=r"(r[1]), "=r"(r[2]), "=r"(r[3]) : "r"(a));
}
__device__ __forceinline__ void mma_bf16(float* d, const uint32_t* a, const uint32_t* b) {
    asm volatile(
        "mma.sync.aligned.m16n8k16.row.col.f32.bf16.bf16.f32 "
        "{%0,%1,%2,%3}, {%4,%5,%6,%7}, {%8,%9}, {%0,%1,%2,%3};"
        : "+f"(d[0]), "+f"(d[1]), "+f"(d[2]), "+f"(d[3])
        : "r"(a[0]), "r"(a[1]), "r"(a[2]), "r"(a[3]), "r"(b[0]), "r"(b[1]));
}
__device__ __forceinline__ void mma_f16(float* d, const uint32_t* a, const uint32_t* b) {
    asm volatile(
        "mma.sync.aligned.m16n8k16.row.col.f32.f16.f16.f32 "
        "{%0,%1,%2,%3}, {%4,%5,%6,%7}, {%8,%9}, {%0,%1,%2,%3};"
        : "+f"(d[0]), "+f"(d[1]), "+f"(d[2]), "+f"(d[3])
        : "r"(a[0]), "r"(a[1]), "r"(a[2]), "r"(a[3]), "r"(b[0]), "r"(b[1]));
}
// bf16 hi/lo split (packed pairs)
__device__ __forceinline__ void cvt2(float x0, float x1, uint32_t& hi, uint32_t& lo) {
    __nv_bfloat162 h = __float22bfloat162_rn(make_float2(x0, x1));
    hi = *reinterpret_cast<uint32_t*>(&h);
    float h0 = __uint_as_float(hi << 16);
    float h1 = __uint_as_float(hi & 0xFFFF0000u);
    __nv_bfloat162 l = __float22bfloat162_rn(make_float2(x0 - h0, x1 - h1));
    lo = *reinterpret_cast<uint32_t*>(&l);
}
// fp16 single pack
__device__ __forceinline__ uint32_t cvth(float x0, float x1) {
    __half2 h = __float22half2_rn(make_float2(x0, x1));
    return *reinterpret_cast<uint32_t*>(&h);
}

// ---------------------------------------------------------------------------
__global__ __launch_bounds__(THREADS, 2) void attn_mma(
    const float* __restrict__ story_a, const float* __restrict__ u,
    const float* __restrict__ story_c)
{
    extern __shared__ char sm[];
    const uint32_t sb = smem_u32(sm);
    float2* red = reinterpret_cast<float2*>(sm + RED_OFF);   // [row][qh]
    const int tid = threadIdx.x, lane = tid & 31, wid = tid >> 5;
    const int b = blockIdx.y, chunk = blockIdx.x;
    const int m_base_g = chunk * CHUNK;

    // ---- stage u (64q x 128d), bf16 hi/lo, swizzled ----
    {
        const float4* g4 = reinterpret_cast<const float4*>(u + (size_t)b * QN * DN);
        for (int i = tid; i < QN * DN / 4; i += THREADS) {
            int q = i >> 5, j = i & 31;
            float4 v = g4[i];
            uint32_t h0, l0, h1, l1;
            cvt2(v.x, v.y, h0, l0); cvt2(v.z, v.w, h1, l1);
            uint32_t off = swz(q, j >> 1) + (j & 1) * 8;
            *reinterpret_cast<uint2*>(sm + U_HI + off) = make_uint2(h0, h1);
            *reinterpret_cast<uint2*>(sm + U_LO + off) = make_uint2(l0, l1);
        }
    }

    // GEMM1: warp = 16m x 32q.
    const int mg = wid & 3, qh = wid >> 2;
    const uint32_t a1_row = (uint32_t)(mg * 16 + (lane & 15));
    const uint32_t a1_gh  = (lane & 16) ? 1u : 0u;
    const uint32_t b1_row = (uint32_t)((lane & 7) + ((lane & 16) ? 8 : 0));
    const uint32_t b1_gh  = (lane & 8) ? 1u : 0u;
    // GEMM2: warp = 16q x 64d.
    const int qg = wid & 3, dh = wid >> 2;
    const uint32_t pa_row = (uint32_t)((lane & 7) + ((lane & 16) ? 8 : 0));
    const uint32_t pa_g   = (uint32_t)(qg * 2 + ((lane & 8) ? 1 : 0));
    const uint32_t cb_row = (uint32_t)((lane & 7) + ((lane & 8) ? 8 : 0));
    const uint32_t cb_gh  = (lane & 16) ? 1u : 0u;

    float cacc[8][4];
#pragma unroll
    for (int i = 0; i < 8; ++i)
#pragma unroll
        for (int j = 0; j < 4; ++j) cacc[i][j] = 0.f;

    for (int t = 0; t < NT; ++t) {
        // ---- prefetch story_a tile into registers BEFORE the barrier ----
        const float4* ga = reinterpret_cast<const float4*>(
            story_a + ((size_t)b * M_ + m_base_g + t * MT) * DN);
        const float4* gc = reinterpret_cast<const float4*>(
            story_c + ((size_t)b * M_ + m_base_g + t * MT) * DN);
        float4 a_pre[8];
#pragma unroll
        for (int k = 0; k < 8; ++k) a_pre[k] = ga[tid + k * THREADS];

        __syncthreads();   // previous tile fully consumed

        // ---- issue story_c loads, then convert+store A (hides C latency) ----
        {
            float4 c_pre[8];
#pragma unroll
            for (int k = 0; k < 8; ++k) c_pre[k] = gc[tid + k * THREADS];
#pragma unroll
            for (int k = 0; k < 8; ++k) {
                int i = tid + k * THREADS;
                int m = i >> 5, j = i & 31;
                uint32_t off = swz(m, j >> 1) + (j & 1) * 8;
                uint32_t h0, l0, h1, l1;
                cvt2(a_pre[k].x, a_pre[k].y, h0, l0);
                cvt2(a_pre[k].z, a_pre[k].w, h1, l1);
                *reinterpret_cast<uint2*>(sm + A_HI + off) = make_uint2(h0, h1);
                *reinterpret_cast<uint2*>(sm + A_LO + off) = make_uint2(l0, l1);
            }
#pragma unroll
            for (int k = 0; k < 8; ++k) {
                int i = tid + k * THREADS;
                int m = i >> 5, j = i & 31;
                uint32_t off = swz(m, j >> 1) + (j & 1) * 8;
                *reinterpret_cast<uint2*>(sm + C_F + off) =
                    make_uint2(cvth(c_pre[k].x, c_pre[k].y), cvth(c_pre[k].z, c_pre[k].w));
            }
        }
        __syncthreads();

        // ---- GEMM1: S[16m][32q], bf16 3-pass, K=128, A-frag double-buffered ----
        float s[4][4];
#pragma unroll
        for (int i = 0; i < 4; ++i)
#pragma unroll
            for (int j = 0; j < 4; ++j) s[i][j] = 0.f;

        uint32_t ahb[2][4], alb[2][4];
        {
            uint32_t a0 = sb + A_HI + swz(a1_row, a1_gh);
            ldsm4(ahb[0], a0);
            ldsm4(alb[0], a0 + (A_LO - A_HI));
        }
#pragma unroll
        for (int ks = 0; ks < 8; ++ks) {
            const int cur = ks & 1, nxt = cur ^ 1;
            if (ks < 7) {
                uint32_t an = sb + A_HI + swz(a1_row, (uint32_t)(ks + 1) * 2 + a1_gh);
                ldsm4(ahb[nxt], an);
                ldsm4(alb[nxt], an + (A_LO - A_HI));
            }
#pragma unroll
            for (int ntp = 0; ntp < 2; ++ntp) {
                uint32_t bh[4], bl[4];
                uint32_t baddr = sb + U_HI
                    + swz((uint32_t)(qh * 32 + ntp * 16) + b1_row, (uint32_t)ks * 2 + b1_gh);
                ldsm4(bh, baddr);
                ldsm4(bl, baddr + (U_LO - U_HI));
#pragma unroll
                for (int j = 0; j < 2; ++j) {
                    mma_bf16(s[ntp * 2 + j], ahb[cur], bh + 2 * j);
                    mma_bf16(s[ntp * 2 + j], ahb[cur], bl + 2 * j);
                    mma_bf16(s[ntp * 2 + j], alb[cur], bh + 2 * j);
                }
            }
        }

        // ---- softmax over q: local stats + one-barrier cross-half merge ----
        {
            const uint32_t r1 = (uint32_t)(mg * 16 + (lane >> 2)), r2 = r1 + 8;
            float mx1 = -1e30f, mx2 = -1e30f;
#pragma unroll
            for (int nt = 0; nt < 4; ++nt) {
                mx1 = fmaxf(mx1, fmaxf(s[nt][0], s[nt][1]));
                mx2 = fmaxf(mx2, fmaxf(s[nt][2], s[nt][3]));
            }
            mx1 = fmaxf(mx1, __shfl_xor_sync(0xffffffffu, mx1, 1));
            mx1 = fmaxf(mx1, __shfl_xor_sync(0xffffffffu, mx1, 2));
            mx2 = fmaxf(mx2, __shfl_xor_sync(0xffffffffu, mx2, 1));
            mx2 = fmaxf(mx2, __shfl_xor_sync(0xffffffffu, mx2, 2));
            float sum1 = 0.f, sum2 = 0.f;
#pragma unroll
            for (int nt = 0; nt < 4; ++nt) {
                s[nt][0] = __expf(s[nt][0] - mx1); sum1 += s[nt][0];
                s[nt][1] = __expf(s[nt][1] - mx1); sum1 += s[nt][1];
                s[nt][2] = __expf(s[nt][2] - mx2); sum2 += s[nt][2];
                s[nt][3] = __expf(s[nt][3] - mx2); sum2 += s[nt][3];
            }
            sum1 += __shfl_xor_sync(0xffffffffu, sum1, 1);
            sum1 += __shfl_xor_sync(0xffffffffu, sum1, 2);
            sum2 += __shfl_xor_sync(0xffffffffu, sum2, 1);
            sum2 += __shfl_xor_sync(0xffffffffu, sum2, 2);
            if ((lane & 3) == 0) {
                red[r1 * 2 + qh] = make_float2(mx1, sum1);
                red[r2 * 2 + qh] = make_float2(mx2, sum2);
            }
            __syncthreads();
            float2 o1 = red[r1 * 2 + (1 - qh)];
            float2 o2 = red[r2 * 2 + (1 - qh)];
            float g1 = fmaxf(mx1, o1.x), g2 = fmaxf(mx2, o2.x);
            float e1 = __expf(mx1 - g1), e2 = __expf(mx2 - g2);
            float f1 = e1 / (sum1 * e1 + o1.y * __expf(o1.x - g1));
            float f2 = e2 / (sum2 * e2 + o2.y * __expf(o2.x - g2));

            const uint32_t qb = (uint32_t)(lane & 3) * 4;
#pragma unroll
            for (int nt = 0; nt < 4; ++nt) {
                uint32_t g = (uint32_t)(qh * 4 + nt);
                uint32_t o1b = swzp(r1, g) + qb;
                uint32_t o2b = swzp(r2, g) + qb;
                *reinterpret_cast<uint32_t*>(sm + P_F + o1b) =
                    cvth(s[nt][0] * f1, s[nt][1] * f1);
                *reinterpret_cast<uint32_t*>(sm + P_F + o2b) =
                    cvth(s[nt][2] * f2, s[nt][3] * f2);
            }
        }
        __syncthreads();

        // ---- GEMM2: C[16q][64d] += P^T * SC, fp16 SINGLE-pass, K=64 ----
        uint32_t phb[2][4];
        {
            uint32_t p0 = sb + P_F + swzp(pa_row, pa_g);
            ldsm4t(phb[0], p0);
        }
#pragma unroll
        for (int ks = 0; ks < 4; ++ks) {
            const int cur = ks & 1, nxt = cur ^ 1;
            if (ks < 3) {
                uint32_t pn = sb + P_F + swzp((uint32_t)(ks + 1) * 16 + pa_row, pa_g);
                ldsm4t(phb[nxt], pn);
            }
#pragma unroll
            for (int ntp = 0; ntp < 4; ++ntp) {
                uint32_t bf[4];
                uint32_t baddr = sb + C_F
                    + swz((uint32_t)ks * 16 + cb_row, (uint32_t)(dh * 8 + ntp * 2) + cb_gh);
                ldsm4t(bf, baddr);
#pragma unroll
                for (int j = 0; j < 2; ++j)
                    mma_f16(cacc[ntp * 2 + j], phb[cur], bf + 2 * j);
            }
        }
    }

    // ---- write partials ----
    {
        float* part = g_part + (size_t)(b * S_CHUNKS + chunk) * (QN * DN);
        const int q1 = qg * 16 + (lane >> 2), q2 = q1 + 8;
#pragma unroll
        for (int nt = 0; nt < 8; ++nt) {
            int d0 = dh * 64 + (nt >> 1) * 16 + (nt & 1) * 8 + (lane & 3) * 2;
            *reinterpret_cast<float2*>(part + q1 * DN + d0) =
                make_float2(cacc[nt][0], cacc[nt][1]);
            *reinterpret_cast<float2*>(part + q2 * DN + d0) =
                make_float2(cacc[nt][2], cacc[nt][3]);
        }
    }
}

// ---------------------------------------------------------------------------
// out[b,q,:] = u[b,q,:] @ H + sum_ch g_part[b,ch,q,:]
// 256 CTAs x 256 thr; warp = one (b,q) row. H + 8 u-rows staged in smem.
// Partial-sum LDGs issued before the barrier; consumed after the FFMA loop.
// ---------------------------------------------------------------------------
#define OUT_SMEM ((DN * DN + 8 * DN) * 4)   // 69632
__global__ __launch_bounds__(256) void out_kernel(
    const float* __restrict__ u, const float* __restrict__ H, float* __restrict__ out)
{
    extern __shared__ float sh[];
    float* Hs = sh;              // 128 x 128
    float* us = sh + DN * DN;    // 8 x 128
    const int blk = blockIdx.x, tid = threadIdx.x;
    const int lane = tid & 31, wid = tid >> 5;

    {
        const float4* H4 = reinterpret_cast<const float4*>(H);
        float4* Hs4 = reinterpret_cast<float4*>(Hs);
#pragma unroll
        for (int i = 0; i < 16; ++i) Hs4[tid + i * 256] = H4[tid + i * 256];
        const float4* u4 = reinterpret_cast<const float4*>(u + (size_t)blk * 8 * DN);
        reinterpret_cast<float4*>(us)[tid] = u4[tid];
    }

    // issue partial-sum loads early (independent of smem)
    const int row = blk * 8 + wid;            // global (b,q) row
    const int b = row >> 6, q = row & 63;
    const float4* p4 = reinterpret_cast<const float4*>(g_part);
    const size_t base = (size_t)b * S_CHUNKS * 2048 + (size_t)q * 32 + lane;
    float4 pr[S_CHUNKS];
#pragma unroll
    for (int ch = 0; ch < S_CHUNKS; ++ch)
        pr[ch] = p4[base + (size_t)ch * 2048];

    __syncthreads();

    const float4* Hs4 = reinterpret_cast<const float4*>(Hs);
    const float* up = us + wid * DN;
    float4 acc = make_float4(0.f, 0.f, 0.f, 0.f);
#pragma unroll 16
    for (int e = 0; e < DN; ++e) {
        float4 h = Hs4[e * 32 + lane];
        float x = up[e];
        acc.x += x * h.x; acc.y += x * h.y; acc.z += x * h.z; acc.w += x * h.w;
    }
#pragma unroll
    for (int ch = 0; ch < S_CHUNKS; ++ch) {
        acc.x += pr[ch].x; acc.y += pr[ch].y;
        acc.z += pr[ch].z; acc.w += pr[ch].w;
    }
    reinterpret_cast<float4*>(out)[(size_t)row * 32 + lane] = acc;
}

// ---------------------------------------------------------------------------
extern "C" void kernel_launch(void* const* d_in, const int* in_sizes, int n_in,
                              void* d_out, int out_size)
{
    (void)in_sizes; (void)n_in; (void)out_size;
    const float* story_a = (const float*)d_in[0];
    const float* u       = (const float*)d_in[1];
    const float* story_c = (const float*)d_in[2];
    const float* H       = (const float*)d_in[3];
    float* out = (float*)d_out;

    cudaFuncSetAttribute(attn_mma, cudaFuncAttributeMaxDynamicSharedMemorySize, SMEM_TOTAL);
    dim3 grid(S_CHUNKS, B_);
    attn_mma<<<grid, THREADS, SMEM_TOTAL>>>(story_a, u, story_c);

    cudaFuncSetAttribute(out_kernel, cudaFuncAttributeMaxDynamicSharedMemorySize, OUT_SMEM);
    out_kernel<<<B_ * QN / 8, 256, OUT_SMEM>>>(u, H, out);
}

// round 17
// speedup vs baseline: 1.2316x; 1.0415x over previous
#include <cuda_runtime.h>
#include <cuda_bf16.h>
#include <cuda_fp16.h>
#include <cstdint>

#define B_ 32
#define M_ 8192
#define QN 64
#define DN 128
#define S_CHUNKS 9          // 7 chunks x 14 tiles + 2 chunks x 15 tiles = 128 tiles
#define MT 64
#define THREADS 256

#define ROW  256   // A/C/U row bytes (128 elems x 2B), XOR-swizzled 16B granules
#define PROW 128   // P row bytes (64 elems x 2B)

// shared memory byte offsets (91136 B -> 2 CTAs/SM)
#define A_HI 0
#define A_LO 16384
#define C_F  32768
#define U_HI 49152
#define U_LO 65536
#define P_F  81920
#define RED_OFF 90112
#define SMEM_TOTAL (90112 + 1024)

// partial sums: [b*S_CHUNKS+chunk][q*DN+d]  (9.4 MB)
__device__ float g_part[(size_t)B_ * S_CHUNKS * QN * DN];

__device__ __forceinline__ uint32_t smem_u32(const void* p) {
    uint32_t a;
    asm("{ .reg .u64 t; cvta.to.shared.u64 t, %1; cvt.u32.u64 %0, t; }" : "=r"(a) : "l"(p));
    return a;
}
__device__ __forceinline__ uint32_t swz(uint32_t r, uint32_t g) {
    return r * ROW + ((g ^ (r & 7)) << 4);
}
__device__ __forceinline__ uint32_t swzp(uint32_t r, uint32_t g) {
    return r * PROW + ((g ^ (r & 7)) << 4);
}
__device__ __forceinline__ void ldsm4(uint32_t* r, uint32_t a) {
    asm volatile("ldmatrix.sync.aligned.m8n8.x4.shared.b16 {%0,%1,%2,%3}, [%4];"
                 : "=r"(r[0]), "=r"(r[1]), "=r"(r[2]), "=r"(r[3]) : "r"(a));
}
__device__ __forceinline__ void ldsm4t(uint32_t* r, uint32_t a) {
    asm volatile("ldmatrix.sync.aligned.m8n8.x4.trans.shared.b16 {%0,%1,%2,%3}, [%4];"
                 : "=r"(r[0]), "=r"(r[1]), "=r"(r[2]), "=r"(r[3]) : "r"(a));
}
__device__ __forceinline__ void mma_bf16(float* d, const uint32_t* a, const uint32_t* b) {
    asm volatile(
        "mma.sync.aligned.m16n8k16.row.col.f32.bf16.bf16.f32 "
        "{%0,%1,%2,%3}, {%4,%5,%6,%7}, {%8,%9}, {%0,%1,%2,%3};"
        : "+f"(d[0]), "+f"(d[1]), "+f"(d[2]), "+f"(d[3])
        : "r"(a[0]), "r"(a[1]), "r"(a[2]), "r"(a[3]), "r"(b[0]), "r"(b[1]));
}
__device__ __forceinline__ void mma_f16(float* d, const uint32_t* a, const uint32_t* b) {
    asm volatile(
        "mma.sync.aligned.m16n8k16.row.col.f32.f16.f16.f32 "
        "{%0,%1,%2,%3}, {%4,%5,%6,%7}, {%8,%9}, {%0,%1,%2,%3};"
        : "+f"(d[0]), "+f"(d[1]), "+f"(d[2]), "+f"(d[3])
        : "r"(a[0]), "r"(a[1]), "r"(a[2]), "r"(a[3]), "r"(b[0]), "r"(b[1]));
}
// bf16 hi/lo split (packed pairs)
__device__ __forceinline__ void cvt2(float x0, float x1, uint32_t& hi, uint32_t& lo) {
    __nv_bfloat162 h = __float22bfloat162_rn(make_float2(x0, x1));
    hi = *reinterpret_cast<uint32_t*>(&h);
    float h0 = __uint_as_float(hi << 16);
    float h1 = __uint_as_float(hi & 0xFFFF0000u);
    __nv_bfloat162 l = __float22bfloat162_rn(make_float2(x0 - h0, x1 - h1));
    lo = *reinterpret_cast<uint32_t*>(&l);
}
// fp16 single pack
__device__ __forceinline__ uint32_t cvth(float x0, float x1) {
    __half2 h = __float22half2_rn(make_float2(x0, x1));
    return *reinterpret_cast<uint32_t*>(&h);
}

// ---------------------------------------------------------------------------
__global__ __launch_bounds__(THREADS, 2) void attn_mma(
    const float* __restrict__ story_a, const float* __restrict__ u,
    const float* __restrict__ story_c)
{
    extern __shared__ char sm[];
    const uint32_t sb = smem_u32(sm);
    float2* red = reinterpret_cast<float2*>(sm + RED_OFF);   // [row][qh]
    const int tid = threadIdx.x, lane = tid & 31, wid = tid >> 5;
    const int b = blockIdx.y, chunk = blockIdx.x;
    // uneven static split: chunks 0..6 -> 14 tiles, chunks 7..8 -> 15 tiles
    const int tbase = chunk * 14 + (chunk >= 7 ? chunk - 7 : 0);
    const int nt    = 14 + (chunk >= 7 ? 1 : 0);
    const int m_base_g = tbase * MT;

    // ---- stage u (64q x 128d), bf16 hi/lo, swizzled ----
    {
        const float4* g4 = reinterpret_cast<const float4*>(u + (size_t)b * QN * DN);
        for (int i = tid; i < QN * DN / 4; i += THREADS) {
            int q = i >> 5, j = i & 31;
            float4 v = g4[i];
            uint32_t h0, l0, h1, l1;
            cvt2(v.x, v.y, h0, l0); cvt2(v.z, v.w, h1, l1);
            uint32_t off = swz(q, j >> 1) + (j & 1) * 8;
            *reinterpret_cast<uint2*>(sm + U_HI + off) = make_uint2(h0, h1);
            *reinterpret_cast<uint2*>(sm + U_LO + off) = make_uint2(l0, l1);
        }
    }

    // GEMM1: warp = 16m x 32q.
    const int mg = wid & 3, qh = wid >> 2;
    const uint32_t a1_row = (uint32_t)(mg * 16 + (lane & 15));
    const uint32_t a1_gh  = (lane & 16) ? 1u : 0u;
    const uint32_t b1_row = (uint32_t)((lane & 7) + ((lane & 16) ? 8 : 0));
    const uint32_t b1_gh  = (lane & 8) ? 1u : 0u;
    // GEMM2: warp = 16q x 64d.
    const int qg = wid & 3, dh = wid >> 2;
    const uint32_t pa_row = (uint32_t)((lane & 7) + ((lane & 16) ? 8 : 0));
    const uint32_t pa_g   = (uint32_t)(qg * 2 + ((lane & 8) ? 1 : 0));
    const uint32_t cb_row = (uint32_t)((lane & 7) + ((lane & 8) ? 8 : 0));
    const uint32_t cb_gh  = (lane & 16) ? 1u : 0u;

    float cacc[8][4];
#pragma unroll
    for (int i = 0; i < 8; ++i)
#pragma unroll
        for (int j = 0; j < 4; ++j) cacc[i][j] = 0.f;

    for (int t = 0; t < nt; ++t) {
        // ---- prefetch story_a tile into registers BEFORE the barrier ----
        const float4* ga = reinterpret_cast<const float4*>(
            story_a + ((size_t)b * M_ + m_base_g + t * MT) * DN);
        const float4* gc = reinterpret_cast<const float4*>(
            story_c + ((size_t)b * M_ + m_base_g + t * MT) * DN);
        float4 a_pre[8];
#pragma unroll
        for (int k = 0; k < 8; ++k) a_pre[k] = ga[tid + k * THREADS];

        __syncthreads();   // previous tile fully consumed

        // ---- issue story_c loads, then convert+store A (hides C latency) ----
        {
            float4 c_pre[8];
#pragma unroll
            for (int k = 0; k < 8; ++k) c_pre[k] = gc[tid + k * THREADS];
#pragma unroll
            for (int k = 0; k < 8; ++k) {
                int i = tid + k * THREADS;
                int m = i >> 5, j = i & 31;
                uint32_t off = swz(m, j >> 1) + (j & 1) * 8;
                uint32_t h0, l0, h1, l1;
                cvt2(a_pre[k].x, a_pre[k].y, h0, l0);
                cvt2(a_pre[k].z, a_pre[k].w, h1, l1);
                *reinterpret_cast<uint2*>(sm + A_HI + off) = make_uint2(h0, h1);
                *reinterpret_cast<uint2*>(sm + A_LO + off) = make_uint2(l0, l1);
            }
#pragma unroll
            for (int k = 0; k < 8; ++k) {
                int i = tid + k * THREADS;
                int m = i >> 5, j = i & 31;
                uint32_t off = swz(m, j >> 1) + (j & 1) * 8;
                *reinterpret_cast<uint2*>(sm + C_F + off) =
                    make_uint2(cvth(c_pre[k].x, c_pre[k].y), cvth(c_pre[k].z, c_pre[k].w));
            }
        }
        __syncthreads();

        // ---- GEMM1: S[16m][32q], bf16 3-pass, K=128, A-frag double-buffered ----
        float s[4][4];
#pragma unroll
        for (int i = 0; i < 4; ++i)
#pragma unroll
            for (int j = 0; j < 4; ++j) s[i][j] = 0.f;

        uint32_t ahb[2][4], alb[2][4];
        {
            uint32_t a0 = sb + A_HI + swz(a1_row, a1_gh);
            ldsm4(ahb[0], a0);
            ldsm4(alb[0], a0 + (A_LO - A_HI));
        }
#pragma unroll
        for (int ks = 0; ks < 8; ++ks) {
            const int cur = ks & 1, nxt = cur ^ 1;
            if (ks < 7) {
                uint32_t an = sb + A_HI + swz(a1_row, (uint32_t)(ks + 1) * 2 + a1_gh);
                ldsm4(ahb[nxt], an);
                ldsm4(alb[nxt], an + (A_LO - A_HI));
            }
#pragma unroll
            for (int ntp = 0; ntp < 2; ++ntp) {
                uint32_t bh[4], bl[4];
                uint32_t baddr = sb + U_HI
                    + swz((uint32_t)(qh * 32 + ntp * 16) + b1_row, (uint32_t)ks * 2 + b1_gh);
                ldsm4(bh, baddr);
                ldsm4(bl, baddr + (U_LO - U_HI));
#pragma unroll
                for (int j = 0; j < 2; ++j) {
                    mma_bf16(s[ntp * 2 + j], ahb[cur], bh + 2 * j);
                    mma_bf16(s[ntp * 2 + j], ahb[cur], bl + 2 * j);
                    mma_bf16(s[ntp * 2 + j], alb[cur], bh + 2 * j);
                }
            }
        }

        // ---- softmax over q: local stats + one-barrier cross-half merge ----
        {
            const uint32_t r1 = (uint32_t)(mg * 16 + (lane >> 2)), r2 = r1 + 8;
            float mx1 = -1e30f, mx2 = -1e30f;
#pragma unroll
            for (int nt2 = 0; nt2 < 4; ++nt2) {
                mx1 = fmaxf(mx1, fmaxf(s[nt2][0], s[nt2][1]));
                mx2 = fmaxf(mx2, fmaxf(s[nt2][2], s[nt2][3]));
            }
            mx1 = fmaxf(mx1, __shfl_xor_sync(0xffffffffu, mx1, 1));
            mx1 = fmaxf(mx1, __shfl_xor_sync(0xffffffffu, mx1, 2));
            mx2 = fmaxf(mx2, __shfl_xor_sync(0xffffffffu, mx2, 1));
            mx2 = fmaxf(mx2, __shfl_xor_sync(0xffffffffu, mx2, 2));
            float sum1 = 0.f, sum2 = 0.f;
#pragma unroll
            for (int nt2 = 0; nt2 < 4; ++nt2) {
                s[nt2][0] = __expf(s[nt2][0] - mx1); sum1 += s[nt2][0];
                s[nt2][1] = __expf(s[nt2][1] - mx1); sum1 += s[nt2][1];
                s[nt2][2] = __expf(s[nt2][2] - mx2); sum2 += s[nt2][2];
                s[nt2][3] = __expf(s[nt2][3] - mx2); sum2 += s[nt2][3];
            }
            sum1 += __shfl_xor_sync(0xffffffffu, sum1, 1);
            sum1 += __shfl_xor_sync(0xffffffffu, sum1, 2);
            sum2 += __shfl_xor_sync(0xffffffffu, sum2, 1);
            sum2 += __shfl_xor_sync(0xffffffffu, sum2, 2);
            if ((lane & 3) == 0) {
                red[r1 * 2 + qh] = make_float2(mx1, sum1);
                red[r2 * 2 + qh] = make_float2(mx2, sum2);
            }
            __syncthreads();
            float2 o1 = red[r1 * 2 + (1 - qh)];
            float2 o2 = red[r2 * 2 + (1 - qh)];
            float g1 = fmaxf(mx1, o1.x), g2 = fmaxf(mx2, o2.x);
            float e1 = __expf(mx1 - g1), e2 = __expf(mx2 - g2);
            float f1 = e1 / (sum1 * e1 + o1.y * __expf(o1.x - g1));
            float f2 = e2 / (sum2 * e2 + o2.y * __expf(o2.x - g2));

            const uint32_t qb = (uint32_t)(lane & 3) * 4;
#pragma unroll
            for (int nt2 = 0; nt2 < 4; ++nt2) {
                uint32_t g = (uint32_t)(qh * 4 + nt2);
                uint32_t o1b = swzp(r1, g) + qb;
                uint32_t o2b = swzp(r2, g) + qb;
                *reinterpret_cast<uint32_t*>(sm + P_F + o1b) =
                    cvth(s[nt2][0] * f1, s[nt2][1] * f1);
                *reinterpret_cast<uint32_t*>(sm + P_F + o2b) =
                    cvth(s[nt2][2] * f2, s[nt2][3] * f2);
            }
        }
        __syncthreads();

        // ---- GEMM2: C[16q][64d] += P^T * SC, fp16 SINGLE-pass, K=64 ----
        uint32_t phb[2][4];
        {
            uint32_t p0 = sb + P_F + swzp(pa_row, pa_g);
            ldsm4t(phb[0], p0);
        }
#pragma unroll
        for (int ks = 0; ks < 4; ++ks) {
            const int cur = ks & 1, nxt = cur ^ 1;
            if (ks < 3) {
                uint32_t pn = sb + P_F + swzp((uint32_t)(ks + 1) * 16 + pa_row, pa_g);
                ldsm4t(phb[nxt], pn);
            }
#pragma unroll
            for (int ntp = 0; ntp < 4; ++ntp) {
                uint32_t bf[4];
                uint32_t baddr = sb + C_F
                    + swz((uint32_t)ks * 16 + cb_row, (uint32_t)(dh * 8 + ntp * 2) + cb_gh);
                ldsm4t(bf, baddr);
#pragma unroll
                for (int j = 0; j < 2; ++j)
                    mma_f16(cacc[ntp * 2 + j], phb[cur], bf + 2 * j);
            }
        }
    }

    // ---- write partials ----
    {
        float* part = g_part + (size_t)(b * S_CHUNKS + chunk) * (QN * DN);
        const int q1 = qg * 16 + (lane >> 2), q2 = q1 + 8;
#pragma unroll
        for (int nt2 = 0; nt2 < 8; ++nt2) {
            int d0 = dh * 64 + (nt2 >> 1) * 16 + (nt2 & 1) * 8 + (lane & 3) * 2;
            *reinterpret_cast<float2*>(part + q1 * DN + d0) =
                make_float2(cacc[nt2][0], cacc[nt2][1]);
            *reinterpret_cast<float2*>(part + q2 * DN + d0) =
                make_float2(cacc[nt2][2], cacc[nt2][3]);
        }
    }
}

// ---------------------------------------------------------------------------
// out[b,q,:] = u[b,q,:] @ H + sum_ch g_part[b,ch,q,:]
// 256 CTAs x 256 thr; warp = one (b,q) row. H + 8 u-rows staged in smem.
// ---------------------------------------------------------------------------
#define OUT_SMEM ((DN * DN + 8 * DN) * 4)   // 69632
__global__ __launch_bounds__(256) void out_kernel(
    const float* __restrict__ u, const float* __restrict__ H, float* __restrict__ out)
{
    extern __shared__ float sh[];
    float* Hs = sh;              // 128 x 128
    float* us = sh + DN * DN;    // 8 x 128
    const int blk = blockIdx.x, tid = threadIdx.x;
    const int lane = tid & 31, wid = tid >> 5;

    {
        const float4* H4 = reinterpret_cast<const float4*>(H);
        float4* Hs4 = reinterpret_cast<float4*>(Hs);
#pragma unroll
        for (int i = 0; i < 16; ++i) Hs4[tid + i * 256] = H4[tid + i * 256];
        const float4* u4 = reinterpret_cast<const float4*>(u + (size_t)blk * 8 * DN);
        reinterpret_cast<float4*>(us)[tid] = u4[tid];
    }

    // issue partial-sum loads early (independent of smem)
    const int row = blk * 8 + wid;            // global (b,q) row
    const int b = row >> 6, q = row & 63;
    const float4* p4 = reinterpret_cast<const float4*>(g_part);
    const size_t base = (size_t)b * S_CHUNKS * 2048 + (size_t)q * 32 + lane;
    float4 pr[S_CHUNKS];
#pragma unroll
    for (int ch = 0; ch < S_CHUNKS; ++ch)
        pr[ch] = p4[base + (size_t)ch * 2048];

    __syncthreads();

    const float4* Hs4 = reinterpret_cast<const float4*>(Hs);
    const float* up = us + wid * DN;
    float4 acc = make_float4(0.f, 0.f, 0.f, 0.f);
#pragma unroll 16
    for (int e = 0; e < DN; ++e) {
        float4 h = Hs4[e * 32 + lane];
        float x = up[e];
        acc.x += x * h.x; acc.y += x * h.y; acc.z += x * h.z; acc.w += x * h.w;
    }
#pragma unroll
    for (int ch = 0; ch < S_CHUNKS; ++ch) {
        acc.x += pr[ch].x; acc.y += pr[ch].y;
        acc.z += pr[ch].z; acc.w += pr[ch].w;
    }
    reinterpret_cast<float4*>(out)[(size_t)row * 32 + lane] = acc;
}

// ---------------------------------------------------------------------------
extern "C" void kernel_launch(void* const* d_in, const int* in_sizes, int n_in,
                              void* d_out, int out_size)
{
    (void)in_sizes; (void)n_in; (void)out_size;
    const float* story_a = (const float*)d_in[0];
    const float* u       = (const float*)d_in[1];
    const float* story_c = (const float*)d_in[2];
    const float* H       = (const float*)d_in[3];
    float* out = (float*)d_out;

    cudaFuncSetAttribute(attn_mma, cudaFuncAttributeMaxDynamicSharedMemorySize, SMEM_TOTAL);
    dim3 grid(S_CHUNKS, B_);
    attn_mma<<<grid, THREADS, SMEM_TOTAL>>>(story_a, u, story_c);

    cudaFuncSetAttribute(out_kernel, cudaFuncAttributeMaxDynamicSharedMemorySize, OUT_SMEM);
    out_kernel<<<B_ * QN / 8, 256, OUT_SMEM>>>(u, H, out);
}